// round 13
// baseline (speedup 1.0000x reference)
#include <cuda_runtime.h>
#include <cuda_bf16.h>

// Segment-sum of weighted RGB over sorted ray indices. Two-pass, ZERO atomics.
//   Pass 1: boundary scan over sorted ray_indices -> seg_start[r] (device scratch).
//   Pass 2: one warp per ray; lanes stride the segment, shuffle-reduce, plain STG.
// No zero-init needed: every output element is written exactly once.

#define MAX_RAYS 65536
__device__ int g_seg_start[MAX_RAYS + 1];

#define BLOCK1 256
#define BLOCK2 256
#define WARPS2 (BLOCK2 / 32)

__global__ __launch_bounds__(BLOCK1) void boundary_kernel(
    const int* __restrict__ idx, int n_samples, int n_rays)
{
    int i = blockIdx.x * blockDim.x + threadIdx.x;
    if (i >= n_samples) return;
    int v = idx[i];
    int prev = __shfl_up_sync(0xffffffffu, v, 1);
    if ((threadIdx.x & 31) == 0)
        prev = (i == 0) ? -1 : idx[i - 1];
    if (prev != v) {
        // rays (prev, v] start at sample i  (indices are sorted, so prev < v)
        if (prev < -1) prev = -1;
        if (v > n_rays - 1) v = n_rays - 1;
        for (int r = prev + 1; r <= v; r++)
            g_seg_start[r] = i;
    }
    if (i == n_samples - 1) {
        int vv = v < 0 ? 0 : v;
        for (int r = vv + 1; r <= n_rays; r++)
            g_seg_start[r] = n_samples;
    }
}

__global__ __launch_bounds__(BLOCK2) void integrate_kernel(
    const float* __restrict__ rgbf,   // [N*3]
    const float* __restrict__ wf,     // [N]
    float* __restrict__ out,          // [n_rays*3]
    int n_rays)
{
    const int warp = threadIdx.x >> 5;
    const int lane = threadIdx.x & 31;
    const int ray  = blockIdx.x * WARPS2 + warp;
    if (ray >= n_rays) return;

    const int s0 = g_seg_start[ray];
    const int s1 = g_seg_start[ray + 1];

    float a0 = 0.f, a1 = 0.f, a2 = 0.f;
    // two independent streams for MLP (avg segment = 64 -> 2 iters/lane)
    float b0 = 0.f, b1 = 0.f, b2 = 0.f;
    int s = s0 + lane;
    for (; s + 32 < s1; s += 64) {
        float wa = wf[s];
        float wb = wf[s + 32];
        float ra0 = rgbf[3 * s + 0], ra1 = rgbf[3 * s + 1], ra2 = rgbf[3 * s + 2];
        float rb0 = rgbf[3 * (s + 32) + 0], rb1 = rgbf[3 * (s + 32) + 1], rb2 = rgbf[3 * (s + 32) + 2];
        a0 = fmaf(wa, ra0, a0); a1 = fmaf(wa, ra1, a1); a2 = fmaf(wa, ra2, a2);
        b0 = fmaf(wb, rb0, b0); b1 = fmaf(wb, rb1, b1); b2 = fmaf(wb, rb2, b2);
    }
    if (s < s1) {
        float wa = wf[s];
        a0 = fmaf(wa, rgbf[3 * s + 0], a0);
        a1 = fmaf(wa, rgbf[3 * s + 1], a1);
        a2 = fmaf(wa, rgbf[3 * s + 2], a2);
    }
    a0 += b0; a1 += b1; a2 += b2;

    // warp reduction
#pragma unroll
    for (int off = 16; off > 0; off >>= 1) {
        a0 += __shfl_xor_sync(0xffffffffu, a0, off);
        a1 += __shfl_xor_sync(0xffffffffu, a1, off);
        a2 += __shfl_xor_sync(0xffffffffu, a2, off);
    }

    if (lane == 0) {
        out[3 * ray + 0] = a0;
        out[3 * ray + 1] = a1;
        out[3 * ray + 2] = a2;
    }
}

extern "C" void kernel_launch(void* const* d_in, const int* in_sizes, int n_in,
                              void* d_out, int out_size) {
    const float* rgb = (const float*)d_in[0];
    const float* wts = (const float*)d_in[1];
    const int*   idx = (const int*)d_in[2];
    float* out = (float*)d_out;

    int n_samples = in_sizes[2];
    int n_rays = out_size / 3;
    if (n_rays > MAX_RAYS) n_rays = MAX_RAYS;

    // pass 1: segment boundaries
    {
        int blocks = (n_samples + BLOCK1 - 1) / BLOCK1;
        boundary_kernel<<<blocks, BLOCK1>>>(idx, n_samples, n_rays);
    }
    // pass 2: one warp per ray, no atomics
    {
        int blocks = (n_rays + WARPS2 - 1) / WARPS2;
        integrate_kernel<<<blocks, BLOCK2>>>(rgb, wts, out, n_rays);
    }
}